// round 2
// baseline (speedup 1.0000x reference)
#include <cuda_runtime.h>
#include <math.h>
#include <stdint.h>

#define NSAMP 32768
#define FF 8
#define HU 128
#define VV 2048
#define LL 32
#define EE 1024
#define EPSB 1e-5f
#define DTT (1.0f/51360.0f)
#define SIGLEN 584
#define FINALW 9344

// ------------------------- scratch (__device__ globals) -------------------------
__device__ float g_bufA[(size_t)FF*NSAMP*HU];   // layer-2 preacts
__device__ float g_bufB[(size_t)FF*NSAMP*HU];   // layer-3 preacts
__device__ float g_yout[FF*NSAMP];              // output-layer preacts
__device__ float g_cA[FF*HU], g_cB[FF*HU];      // analytic layer-1 BN coeffs
__device__ float g_scl2[FF*HU], g_shf2[FF*HU];
__device__ float g_scl3[FF*HU], g_shf3[FF*HU];
__device__ float g_sclO[FF], g_shfO[FF];
__device__ double g_part[FF*16*2*HU];
__device__ double g_partO[FF*64*2];
__device__ float g_fv[(size_t)LL*FF*VV];
__device__ float g_x[LL*FINALW];

// --------------- x batch stats + analytic layer-1 BN coefficients ---------------
// layer1: y = w*x + b ; mean = w*mx+b ; var = w^2*vx  (exact).
// a1 = relu(cA*x + cB), cA = w*g*rsqrt(w^2*vx+eps), cB = beta - cA*mx.
__global__ void k_xstats(const float* __restrict__ x, const float* __restrict__ Win,
                         const float* __restrict__ gin, const float* __restrict__ betain) {
    __shared__ double rs[1024], rq[1024];
    __shared__ double sm[2];
    int t = threadIdx.x;
    double s = 0.0, q = 0.0;
    for (int i = t; i < NSAMP; i += 1024) { double v = x[i]; s += v; q += v*v; }
    rs[t] = s; rq[t] = q; __syncthreads();
    for (int o = 512; o > 0; o >>= 1) {
        if (t < o) { rs[t] += rs[t+o]; rq[t] += rq[t+o]; }
        __syncthreads();
    }
    if (t == 0) { double mx = rs[0]/(double)NSAMP; sm[0] = mx; sm[1] = rq[0]/(double)NSAMP - mx*mx; }
    __syncthreads();
    double mx = sm[0], vx = sm[1];
    double w  = Win[t];          // [F,HU,1] flat
    double g  = gin[t];
    double be = betain[t];
    double cA = w * g / sqrt(w*w*vx + (double)EPSB);
    g_cA[t] = (float)cA;
    g_cB[t] = (float)(be - cA*mx);
}

// --------------------------- hidden-layer GEMM ----------------------------------
// STAGE 0: A[n][k] = relu(cA[k]*x[n]+cB[k]);      Y -> g_bufA
// STAGE 1: A[n][k] = relu(bufA*scl2+shf2);        Y -> g_bufB
template<int STAGE>
__global__ void __launch_bounds__(256, 2) k_gemm(const float* __restrict__ x,
                                                 const float* __restrict__ Wh) {
    __shared__ float As[32][132];
    __shared__ float Bs[32][132];
    __shared__ float s_scl[HU], s_shf[HU], s_x[128];

    int f = blockIdx.y, m0 = blockIdx.x * 128, tid = threadIdx.x;
    int tx = tid & 15, ty = tid >> 4;

    const float* scl = (STAGE == 0) ? g_cA : g_scl2;
    const float* shf = (STAGE == 0) ? g_cB : g_shf2;
    float* Y = (STAGE == 0) ? g_bufA : g_bufB;

    if (tid < 128) {
        s_scl[tid] = scl[f*HU + tid];
        s_shf[tid] = shf[f*HU + tid];
        if (STAGE == 0) s_x[tid] = x[m0 + tid];
    }
    __syncthreads();

    const float* W = Wh + ((size_t)f*2 + STAGE)*HU*HU;   // [j][k]

    float acc[8][8];
    #pragma unroll
    for (int r = 0; r < 8; r++)
        #pragma unroll
        for (int c = 0; c < 8; c++) acc[r][c] = 0.f;

    for (int k0 = 0; k0 < HU; k0 += 32) {
        #pragma unroll
        for (int i = 0; i < 16; i++) {
            int idx = tid + i*256;
            int kk = idx & 31, n = idx >> 5;
            float a;
            if (STAGE == 0) a = s_x[n]*s_scl[k0+kk] + s_shf[k0+kk];
            else            a = g_bufA[((size_t)f*NSAMP + m0 + n)*HU + k0 + kk]*s_scl[k0+kk] + s_shf[k0+kk];
            As[kk][n] = fmaxf(a, 0.f);
            Bs[kk][n] = W[n*HU + k0 + kk];
        }
        __syncthreads();
        #pragma unroll
        for (int kk = 0; kk < 32; kk++) {
            float a[8], b[8];
            *(float4*)(a)   = *(const float4*)&As[kk][ty*8];
            *(float4*)(a+4) = *(const float4*)&As[kk][ty*8+4];
            *(float4*)(b)   = *(const float4*)&Bs[kk][tx*8];
            *(float4*)(b+4) = *(const float4*)&Bs[kk][tx*8+4];
            #pragma unroll
            for (int r = 0; r < 8; r++)
                #pragma unroll
                for (int c = 0; c < 8; c++)
                    acc[r][c] = fmaf(a[r], b[c], acc[r][c]);
        }
        __syncthreads();
    }
    #pragma unroll
    for (int r = 0; r < 8; r++) {
        size_t base = ((size_t)f*NSAMP + m0 + ty*8 + r)*HU + tx*8;
        *(float4*)&Y[base]   = make_float4(acc[r][0], acc[r][1], acc[r][2], acc[r][3]);
        *(float4*)&Y[base+4] = make_float4(acc[r][4], acc[r][5], acc[r][6], acc[r][7]);
    }
}

// --------------------- per-column batch stats (deterministic) -------------------
template<int STAGE>
__global__ void k_colstats() {
    const float* Y = (STAGE == 0) ? g_bufA : g_bufB;
    int f = blockIdx.y, b = blockIdx.x;
    int c = threadIdx.x & 127, h = threadIdx.x >> 7;
    double s = 0.0, q = 0.0;
    int n0 = b*2048;
    for (int n = n0 + h; n < n0 + 2048; n += 2) {
        double v = Y[((size_t)f*NSAMP + n)*HU + c];
        s += v; q += v*v;
    }
    __shared__ double sh[512];
    sh[threadIdx.x] = s; sh[256 + threadIdx.x] = q;
    __syncthreads();
    if (h == 0) {
        s += sh[c + 128]; q += sh[256 + c + 128];
        g_part[((f*16+b)*2+0)*HU + c] = s;
        g_part[((f*16+b)*2+1)*HU + c] = q;
    }
}

template<int STAGE>
__global__ void k_bncoef(const float* __restrict__ gh, const float* __restrict__ betah) {
    int t = threadIdx.x;             // 1024
    int f = t >> 7, u = t & 127;
    double S = 0.0, Q = 0.0;
    for (int b = 0; b < 16; b++) {
        S += g_part[((f*16+b)*2+0)*HU + u];
        Q += g_part[((f*16+b)*2+1)*HU + u];
    }
    double mean = S/(double)NSAMP;
    double var  = Q/(double)NSAMP - mean*mean;
    double g  = gh[f*2*HU + STAGE*HU + u];
    double be = betah[f*2*HU + STAGE*HU + u];
    double scl = g / sqrt(var + (double)EPSB);
    float* oscl = (STAGE == 0) ? g_scl2 : g_scl3;
    float* oshf = (STAGE == 0) ? g_shf2 : g_shf3;
    oscl[t] = (float)scl;
    oshf[t] = (float)(be - scl*mean);
}

// ---------------------- output layer: dot + stats -------------------------------
__global__ void __launch_bounds__(256) k_out(const float* __restrict__ Wout) {
    int f = blockIdx.y;
    int w = threadIdx.x >> 5, lane = threadIdx.x & 31;
    __shared__ float s_w[HU], s_scl[HU], s_shf[HU];
    if (threadIdx.x < 128) {
        s_w[threadIdx.x]   = Wout[f*HU + threadIdx.x];
        s_scl[threadIdx.x] = g_scl3[f*HU + threadIdx.x];
        s_shf[threadIdx.x] = g_shf3[f*HU + threadIdx.x];
    }
    __syncthreads();
    int wg = blockIdx.x*8 + w;          // 0..511
    int n0 = wg*64;
    float w0 = s_w[lane*4], w1 = s_w[lane*4+1], w2 = s_w[lane*4+2], w3 = s_w[lane*4+3];
    float c0 = s_scl[lane*4], c1 = s_scl[lane*4+1], c2 = s_scl[lane*4+2], c3 = s_scl[lane*4+3];
    float h0 = s_shf[lane*4], h1 = s_shf[lane*4+1], h2 = s_shf[lane*4+2], h3 = s_shf[lane*4+3];
    double s = 0.0, q = 0.0;
    for (int n = n0; n < n0 + 64; n++) {
        float4 y = *(const float4*)&g_bufB[((size_t)f*NSAMP + n)*HU + lane*4];
        float p = fmaxf(fmaf(y.x, c0, h0), 0.f)*w0 + fmaxf(fmaf(y.y, c1, h1), 0.f)*w1
                + fmaxf(fmaf(y.z, c2, h2), 0.f)*w2 + fmaxf(fmaf(y.w, c3, h3), 0.f)*w3;
        #pragma unroll
        for (int o = 16; o > 0; o >>= 1) p += __shfl_down_sync(0xffffffffu, p, o);
        if (lane == 0) { g_yout[f*NSAMP + n] = p; s += p; q += (double)p*p; }
    }
    __shared__ double sh_s[8], sh_q[8];
    if (lane == 0) { sh_s[w] = s; sh_q[w] = q; }
    __syncthreads();
    if (threadIdx.x == 0) {
        double S = 0.0, Q = 0.0;
        for (int i = 0; i < 8; i++) { S += sh_s[i]; Q += sh_q[i]; }
        g_partO[(f*64 + blockIdx.x)*2 + 0] = S;
        g_partO[(f*64 + blockIdx.x)*2 + 1] = Q;
    }
}

__global__ void k_bnO(const float* __restrict__ gout, const float* __restrict__ betaout) {
    int f = threadIdx.x;
    if (f >= FF) return;
    double S = 0.0, Q = 0.0;
    for (int b = 0; b < 64; b++) { S += g_partO[(f*64+b)*2]; Q += g_partO[(f*64+b)*2+1]; }
    double mean = S/(double)NSAMP;
    double var  = Q/(double)NSAMP - mean*mean;
    double scl = (double)gout[f] / sqrt(var + (double)EPSB);
    g_sclO[f] = (float)scl;
    g_shfO[f] = (float)((double)betaout[f] - scl*mean);
}

// ---------------------- einsum: fv[l][f][v] = sum_e evs * eigvec ----------------
__global__ void __launch_bounds__(256) k_einsum(const float* __restrict__ eigvec) {
    int l = blockIdx.y;
    int v0 = blockIdx.x*512 + threadIdx.x*2;
    __shared__ float evs[FF][EE];
    for (int idx = threadIdx.x; idx < FF*EE; idx += 256) {
        int f = idx >> 10, e = idx & 1023;
        float y = g_yout[f*NSAMP + l*EE + e];
        evs[f][e] = fmaxf(fmaf(y, g_sclO[f], g_shfO[f]), 0.f);
    }
    __syncthreads();
    float2 acc[FF];
    #pragma unroll
    for (int f = 0; f < FF; f++) acc[f] = make_float2(0.f, 0.f);
    const float* base = eigvec + ((size_t)l*EE)*VV + v0;
    #pragma unroll 4
    for (int e = 0; e < EE; e++) {
        float2 wv = *(const float2*)(base + (size_t)e*VV);
        #pragma unroll
        for (int f = 0; f < FF; f++) {
            float ev = evs[f][e];
            acc[f].x = fmaf(ev, wv.x, acc[f].x);
            acc[f].y = fmaf(ev, wv.y, acc[f].y);
        }
    }
    #pragma unroll
    for (int f = 0; f < FF; f++)
        *(float2*)&g_fv[((size_t)l*FF + f)*VV + v0] = acc[f];
}

// -------------------- gather + project + sort + level-3 signature ---------------
__global__ void __launch_bounds__(256) k_sig(const int* __restrict__ dgm0,
                                             const int* __restrict__ dgm1rel,
                                             const int* __restrict__ dgm1ext,
                                             const float* __restrict__ Wp,
                                             const float* __restrict__ bp) {
    int bid = blockIdx.x;            // 0..511
    int which = bid & 1;
    int row = bid >> 1;              // l*F + f
    int tid = threadIdx.x;
    __shared__ float vals[640];
    __shared__ float srows[7*512];
    __shared__ float s_w0[7], s_w1[7], s_b[7];
    const float* fvr = g_fv + (size_t)row*VV;
    if (tid < 7) { s_w0[tid] = Wp[tid*2]; s_w1[tid] = Wp[tid*2+1]; s_b[tid] = bp[tid]; }
    for (int t = tid; t < 640; t += 256) {
        int src;
        if (which)        src = dgm1ext[row*640 + t];
        else if (t < 512) src = dgm0[row*512 + t];
        else              src = dgm1rel[row*129 + (128 - (t - 512))];
        vals[t] = fvr[src];
    }
    __syncthreads();
    const float PINF = __int_as_float(0x7f800000);
    for (int idx = tid; idx < 7*512; idx += 256) {
        int s = idx >> 9, p = idx & 511;
        float v = PINF;
        if (p < 320) v = fmaf(vals[2*p], s_w0[s], fmaf(vals[2*p+1], s_w1[s], s_b[s]));
        srows[idx] = v;
    }
    __syncthreads();
    int w = tid >> 5, lane = tid & 31;
    if (w < 7) {
        float* a = srows + w*512;
        for (int k = 2; k <= 512; k <<= 1) {
            for (int j = k >> 1; j > 0; j >>= 1) {
                #pragma unroll 1
                for (int i = lane; i < 512; i += 32) {
                    int ixj = i ^ j;
                    if (ixj > i) {
                        float xv = a[i], yv = a[ixj];
                        if ((xv > yv) == ((i & k) == 0)) { a[i] = yv; a[ixj] = xv; }
                    }
                }
                __syncwarp();
            }
        }
    }
    __syncthreads();
    if (tid < 64) {
        int i = tid >> 3, j = tid & 7;
        float s1i = 0.f, s2ij = 0.f;
        float s3[8];
        #pragma unroll
        for (int kk = 0; kk < 8; kk++) s3[kk] = 0.f;
        float cur[7];
        #pragma unroll
        for (int d = 0; d < 7; d++) cur[d] = srows[d*512];
        float dx[8];
        dx[0] = DTT;
        for (int p = 0; p < 319; p++) {
            #pragma unroll
            for (int d = 0; d < 7; d++) {
                float nx = srows[d*512 + p + 1];
                dx[d+1] = nx - cur[d];
                cur[d] = nx;
            }
            float dxi = dx[i], dxj = dx[j];
            float c = fmaf(dxj, fmaf(dxi, (1.f/6.f), 0.5f*s1i), s2ij);
            #pragma unroll
            for (int kk = 0; kk < 8; kk++) s3[kk] = fmaf(c, dx[kk], s3[kk]);
            s2ij = fmaf(dxj, fmaf(0.5f, dxi, s1i), s2ij);
            s1i += dxi;
        }
        int l = row >> 3, fi = row & 7;
        float* out = g_x + l*FINALW + fi*(2*SIGLEN) + which*SIGLEN;
        if (j == 0) out[i] = s1i;
        out[8 + tid] = s2ij;
        #pragma unroll
        for (int kk = 0; kk < 8; kk++) out[72 + tid*8 + kk] = s3[kk];
    }
}

// ----------------------- final dot + BatchNorm over L=32 ------------------------
__global__ void k_final(const float* __restrict__ Wf, const float* __restrict__ gfin,
                        const float* __restrict__ betafin, float* __restrict__ out) {
    int w = threadIdx.x >> 5, lane = threadIdx.x & 31;   // 32 warps = 32 rows
    const float* xr = g_x + w*FINALW;
    float p = 0.f;
    for (int i = lane; i < FINALW; i += 32) p = fmaf(xr[i], Wf[i], p);
    #pragma unroll
    for (int o = 16; o > 0; o >>= 1) p += __shfl_down_sync(0xffffffffu, p, o);
    __shared__ double s_out[32];
    if (lane == 0) s_out[w] = p;
    __syncthreads();
    __shared__ double sm[2];
    if (threadIdx.x == 0) {
        double S = 0.0, Q = 0.0;
        for (int i = 0; i < 32; i++) { S += s_out[i]; Q += s_out[i]*s_out[i]; }
        double mean = S/32.0;
        sm[0] = mean; sm[1] = Q/32.0 - mean*mean;
    }
    __syncthreads();
    if (threadIdx.x < 32) {
        double r = (s_out[threadIdx.x] - sm[0]) / sqrt(sm[1] + (double)EPSB);
        out[threadIdx.x] = (float)(r*(double)gfin[0] + (double)betafin[0]);
    }
}

// --------------------------------- launcher -------------------------------------
extern "C" void kernel_launch(void* const* d_in, const int* in_sizes, int n_in,
                              void* d_out, int out_size) {
    const float* eigenvalues = (const float*)d_in[0];
    const float* eigvec      = (const float*)d_in[1];
    const int*   dgm0        = (const int*)d_in[2];
    const int*   dgm1rel     = (const int*)d_in[3];
    const int*   dgm1ext     = (const int*)d_in[4];
    const float* mlp_Win     = (const float*)d_in[5];
    const float* mlp_gin     = (const float*)d_in[7];
    const float* mlp_betain  = (const float*)d_in[8];
    const float* mlp_Wh      = (const float*)d_in[9];
    const float* mlp_gh      = (const float*)d_in[11];
    const float* mlp_betah   = (const float*)d_in[12];
    const float* mlp_Wout    = (const float*)d_in[13];
    const float* mlp_gout    = (const float*)d_in[15];
    const float* mlp_betaout = (const float*)d_in[16];
    const float* W_proj      = (const float*)d_in[17];
    const float* b_proj      = (const float*)d_in[18];
    const float* W_fin       = (const float*)d_in[19];
    const float* g_fin       = (const float*)d_in[21];
    const float* beta_fin    = (const float*)d_in[22];
    float* out = (float*)d_out;

    k_xstats<<<1, 1024>>>(eigenvalues, mlp_Win, mlp_gin, mlp_betain);
    k_gemm<0><<<dim3(256, 8), 256>>>(eigenvalues, mlp_Wh);
    k_colstats<0><<<dim3(16, 8), 256>>>();
    k_bncoef<0><<<1, 1024>>>(mlp_gh, mlp_betah);
    k_gemm<1><<<dim3(256, 8), 256>>>(eigenvalues, mlp_Wh);
    k_colstats<1><<<dim3(16, 8), 256>>>();
    k_bncoef<1><<<1, 1024>>>(mlp_gh, mlp_betah);
    k_out<<<dim3(64, 8), 256>>>(mlp_Wout);
    k_bnO<<<1, 32>>>(mlp_gout, mlp_betaout);
    k_einsum<<<dim3(4, 32), 256>>>(eigvec);
    k_sig<<<512, 256>>>(dgm0, dgm1rel, dgm1ext, W_proj, b_proj);
    k_final<<<1, 1024>>>(W_fin, g_fin, beta_fin, out);
}

// round 3
// speedup vs baseline: 1.5349x; 1.5349x over previous
#include <cuda_runtime.h>
#include <math.h>
#include <stdint.h>

#define NSAMP 32768
#define FF 8
#define HU 128
#define VV 2048
#define LL 32
#define EE 1024
#define EPSB 1e-5f
#define DTT (1.0f/51360.0f)
#define SIGLEN 584
#define FINALW 9344

typedef unsigned long long u64;

// ---- packed f32x2 helpers (Blackwell) ----
#define FMA2(d, a, b, c) asm("fma.rn.f32x2 %0, %1, %2, %3;" : "=l"(d) : "l"(a), "l"(b), "l"(c))
#define ADD2(d, a, b)    asm("add.rn.f32x2 %0, %1, %2;" : "=l"(d) : "l"(a), "l"(b))
#define PACKDUPF(out, f) asm("mov.b64 %0, {%1, %1};" : "=l"(out) : "f"(f))
#define UNPACKF(lo, hi, v) asm("mov.b64 {%0, %1}, %2;" : "=f"(lo), "=f"(hi) : "l"(v))

// ------------------------- scratch (__device__ globals) -------------------------
__device__ float g_bufA[(size_t)FF*NSAMP*HU];   // layer-2 preacts
__device__ float g_bufB[(size_t)FF*NSAMP*HU];   // layer-3 preacts
__device__ float g_yout[FF*NSAMP];              // output-layer preacts
__device__ float g_cA[FF*HU], g_cB[FF*HU];      // analytic layer-1 BN coeffs
__device__ float g_scl2[FF*HU], g_shf2[FF*HU];
__device__ float g_scl3[FF*HU], g_shf3[FF*HU];
__device__ float g_sclO[FF], g_shfO[FF];
__device__ float g_partF[(size_t)FF*256*2*128]; // per-block col stat partials
__device__ double g_partO[FF*64*2];
__device__ float g_fv[(size_t)LL*FF*VV];
__device__ float g_x[LL*FINALW];

// --------------- x batch stats + analytic layer-1 BN coefficients ---------------
__global__ void k_xstats(const float* __restrict__ x, const float* __restrict__ Win,
                         const float* __restrict__ gin, const float* __restrict__ betain) {
    __shared__ double rs[1024], rq[1024];
    __shared__ double sm[2];
    int t = threadIdx.x;
    double s = 0.0, q = 0.0;
    for (int i = t; i < NSAMP; i += 1024) { double v = x[i]; s += v; q += v*v; }
    rs[t] = s; rq[t] = q; __syncthreads();
    for (int o = 512; o > 0; o >>= 1) {
        if (t < o) { rs[t] += rs[t+o]; rq[t] += rq[t+o]; }
        __syncthreads();
    }
    if (t == 0) { double mx = rs[0]/(double)NSAMP; sm[0] = mx; sm[1] = rq[0]/(double)NSAMP - mx*mx; }
    __syncthreads();
    double mx = sm[0], vx = sm[1];
    double w  = Win[t];
    double g  = gin[t];
    double be = betain[t];
    double cA = w * g / sqrt(w*w*vx + (double)EPSB);
    g_cA[t] = (float)cA;
    g_cB[t] = (float)(be - cA*mx);
}

// --------------------------- hidden-layer GEMM (f32x2) --------------------------
// STAGE 0: A[n][k] = relu(cA[k]*x[n]+cB[k]);  Y -> g_bufA, stats -> g_partF
// STAGE 1: A[n][k] = relu(bufA*scl2+shf2);    Y -> g_bufB, stats -> g_partF
template<int STAGE>
__global__ void __launch_bounds__(256, 2) k_gemm(const float* __restrict__ x,
                                                 const float* __restrict__ Wh) {
    __shared__ __align__(16) float As[32][132];
    __shared__ __align__(16) float Bs[32][132];
    __shared__ float s_scl[HU], s_shf[HU], s_x[128];

    int f = blockIdx.y, bx = blockIdx.x, m0 = bx * 128, tid = threadIdx.x;
    int tx = tid & 15, ty = tid >> 4;

    const float* scl = (STAGE == 0) ? g_cA : g_scl2;
    const float* shf = (STAGE == 0) ? g_cB : g_shf2;
    float* Y = (STAGE == 0) ? g_bufA : g_bufB;

    if (tid < 128) {
        s_scl[tid] = scl[f*HU + tid];
        s_shf[tid] = shf[f*HU + tid];
        if (STAGE == 0) s_x[tid] = x[m0 + tid];
    }
    __syncthreads();

    const float* W = Wh + ((size_t)f*2 + STAGE)*HU*HU;

    u64 acc[8][4];
    #pragma unroll
    for (int r = 0; r < 8; r++)
        #pragma unroll
        for (int c = 0; c < 4; c++) acc[r][c] = 0ull;

    for (int k0 = 0; k0 < HU; k0 += 32) {
        #pragma unroll
        for (int i = 0; i < 16; i++) {
            int idx = tid + i*256;
            int kk = idx & 31, n = idx >> 5;
            float a;
            if (STAGE == 0) a = s_x[n]*s_scl[k0+kk] + s_shf[k0+kk];
            else            a = g_bufA[((size_t)f*NSAMP + m0 + n)*HU + k0 + kk]*s_scl[k0+kk] + s_shf[k0+kk];
            As[kk][n] = fmaxf(a, 0.f);
            Bs[kk][n] = W[n*HU + k0 + kk];
        }
        __syncthreads();
        #pragma unroll
        for (int kk = 0; kk < 32; kk++) {
            float a[8];
            *(float4*)(a)   = *(const float4*)&As[kk][ty*8];
            *(float4*)(a+4) = *(const float4*)&As[kk][ty*8+4];
            u64 b[4];
            *(ulonglong2*)(b)   = *(const ulonglong2*)&Bs[kk][tx*8];
            *(ulonglong2*)(b+2) = *(const ulonglong2*)&Bs[kk][tx*8+4];
            #pragma unroll
            for (int r = 0; r < 8; r++) {
                u64 a2;
                PACKDUPF(a2, a[r]);
                #pragma unroll
                for (int c = 0; c < 4; c++) FMA2(acc[r][c], a2, b[c], acc[r][c]);
            }
        }
        __syncthreads();
    }

    // stores (packed, columns are adjacent)
    #pragma unroll
    for (int r = 0; r < 8; r++) {
        size_t base = ((size_t)f*NSAMP + m0 + ty*8 + r)*HU + tx*8;
        ulonglong2 v0; v0.x = acc[r][0]; v0.y = acc[r][1];
        ulonglong2 v1; v1.x = acc[r][2]; v1.y = acc[r][3];
        *(ulonglong2*)&Y[base]   = v0;
        *(ulonglong2*)&Y[base+4] = v1;
    }

    // fused column stats: packed sums over this thread's 8 rows
    u64 s2[4], q2[4];
    #pragma unroll
    for (int c = 0; c < 4; c++) { s2[c] = 0ull; q2[c] = 0ull; }
    #pragma unroll
    for (int r = 0; r < 8; r++)
        #pragma unroll
        for (int c = 0; c < 4; c++) {
            ADD2(s2[c], s2[c], acc[r][c]);
            FMA2(q2[c], acc[r][c], acc[r][c], q2[c]);
        }
    __syncthreads();
    u64* sh = (u64*)&As[0][0];          // reuse As: 2048 u64 = 16KB (fits in 16.9KB)
    #pragma unroll
    for (int c = 0; c < 4; c++) {
        sh[(ty*16 + tx)*4 + c]        = s2[c];
        sh[1024 + (ty*16 + tx)*4 + c] = q2[c];
    }
    __syncthreads();
    if (tid < 64) {
        int txx = tid >> 2, cpi = tid & 3;
        u64 S = 0ull, Q = 0ull;
        #pragma unroll
        for (int t2 = 0; t2 < 16; t2++) {
            ADD2(S, S, sh[(t2*16 + txx)*4 + cpi]);
            ADD2(Q, Q, sh[1024 + (t2*16 + txx)*4 + cpi]);
        }
        float slo, shi, qlo, qhi;
        UNPACKF(slo, shi, S);
        UNPACKF(qlo, qhi, Q);
        int col = txx*8 + cpi*2;
        float* P = g_partF + (((size_t)f*256 + bx)*2)*128;
        P[col] = slo; P[col+1] = shi;
        P[128+col] = qlo; P[128+col+1] = qhi;
    }
}

// --------------------- BN coefficients from GEMM partials -----------------------
template<int STAGE>
__global__ void k_bncoef(const float* __restrict__ gh, const float* __restrict__ betah) {
    int f = blockIdx.x;
    int u = threadIdx.x & 127, h = threadIdx.x >> 7;   // h in 0..7
    double S = 0.0, Q = 0.0;
    #pragma unroll 8
    for (int b = h; b < 256; b += 8) {
        const float* P = g_partF + (((size_t)f*256 + b)*2)*128;
        S += P[u]; Q += P[128+u];
    }
    __shared__ double shS[1024], shQ[1024];
    shS[h*128+u] = S; shQ[h*128+u] = Q;
    __syncthreads();
    if (h == 0) {
        #pragma unroll
        for (int i = 1; i < 8; i++) { S += shS[i*128+u]; Q += shQ[i*128+u]; }
        double mean = S/(double)NSAMP;
        double var  = Q/(double)NSAMP - mean*mean;
        double g  = gh[f*2*HU + STAGE*HU + u];
        double be = betah[f*2*HU + STAGE*HU + u];
        double scl = g / sqrt(var + (double)EPSB);
        float* oscl = (STAGE == 0) ? g_scl2 : g_scl3;
        float* oshf = (STAGE == 0) ? g_shf2 : g_shf3;
        oscl[f*HU+u] = (float)scl;
        oshf[f*HU+u] = (float)(be - scl*mean);
    }
}

// ---------------------- output layer: dot + stats -------------------------------
__global__ void __launch_bounds__(256) k_out(const float* __restrict__ Wout) {
    int f = blockIdx.y;
    int w = threadIdx.x >> 5, lane = threadIdx.x & 31;
    __shared__ float s_w[HU], s_scl[HU], s_shf[HU];
    if (threadIdx.x < 128) {
        s_w[threadIdx.x]   = Wout[f*HU + threadIdx.x];
        s_scl[threadIdx.x] = g_scl3[f*HU + threadIdx.x];
        s_shf[threadIdx.x] = g_shf3[f*HU + threadIdx.x];
    }
    __syncthreads();
    int wg = blockIdx.x*8 + w;
    int n0 = wg*64;
    float w0 = s_w[lane*4], w1 = s_w[lane*4+1], w2 = s_w[lane*4+2], w3 = s_w[lane*4+3];
    float c0 = s_scl[lane*4], c1 = s_scl[lane*4+1], c2 = s_scl[lane*4+2], c3 = s_scl[lane*4+3];
    float h0 = s_shf[lane*4], h1 = s_shf[lane*4+1], h2 = s_shf[lane*4+2], h3 = s_shf[lane*4+3];
    double s = 0.0, q = 0.0;
    for (int n = n0; n < n0 + 64; n++) {
        float4 y = *(const float4*)&g_bufB[((size_t)f*NSAMP + n)*HU + lane*4];
        float p = fmaxf(fmaf(y.x, c0, h0), 0.f)*w0 + fmaxf(fmaf(y.y, c1, h1), 0.f)*w1
                + fmaxf(fmaf(y.z, c2, h2), 0.f)*w2 + fmaxf(fmaf(y.w, c3, h3), 0.f)*w3;
        #pragma unroll
        for (int o = 16; o > 0; o >>= 1) p += __shfl_down_sync(0xffffffffu, p, o);
        if (lane == 0) { g_yout[f*NSAMP + n] = p; s += p; q += (double)p*p; }
    }
    __shared__ double sh_s[8], sh_q[8];
    if (lane == 0) { sh_s[w] = s; sh_q[w] = q; }
    __syncthreads();
    if (threadIdx.x == 0) {
        double S = 0.0, Q = 0.0;
        for (int i = 0; i < 8; i++) { S += sh_s[i]; Q += sh_q[i]; }
        g_partO[(f*64 + blockIdx.x)*2 + 0] = S;
        g_partO[(f*64 + blockIdx.x)*2 + 1] = Q;
    }
}

__global__ void k_bnO(const float* __restrict__ gout, const float* __restrict__ betaout) {
    int f = threadIdx.x;
    if (f >= FF) return;
    double S = 0.0, Q = 0.0;
    for (int b = 0; b < 64; b++) { S += g_partO[(f*64+b)*2]; Q += g_partO[(f*64+b)*2+1]; }
    double mean = S/(double)NSAMP;
    double var  = Q/(double)NSAMP - mean*mean;
    double scl = (double)gout[f] / sqrt(var + (double)EPSB);
    g_sclO[f] = (float)scl;
    g_shfO[f] = (float)((double)betaout[f] - scl*mean);
}

// ---------------------- einsum: fv[l][f][v] = sum_e evs * eigvec ----------------
__global__ void __launch_bounds__(256) k_einsum(const float* __restrict__ eigvec) {
    int l = blockIdx.y;
    int v0 = blockIdx.x*512 + threadIdx.x*2;
    __shared__ float evs[FF][EE];
    for (int idx = threadIdx.x; idx < FF*EE; idx += 256) {
        int f = idx >> 10, e = idx & 1023;
        float y = g_yout[f*NSAMP + l*EE + e];
        evs[f][e] = fmaxf(fmaf(y, g_sclO[f], g_shfO[f]), 0.f);
    }
    __syncthreads();
    float2 acc[FF];
    #pragma unroll
    for (int f = 0; f < FF; f++) acc[f] = make_float2(0.f, 0.f);
    const float* base = eigvec + ((size_t)l*EE)*VV + v0;
    #pragma unroll 4
    for (int e = 0; e < EE; e++) {
        float2 wv = *(const float2*)(base + (size_t)e*VV);
        #pragma unroll
        for (int f = 0; f < FF; f++) {
            float ev = evs[f][e];
            acc[f].x = fmaf(ev, wv.x, acc[f].x);
            acc[f].y = fmaf(ev, wv.y, acc[f].y);
        }
    }
    #pragma unroll
    for (int f = 0; f < FF; f++)
        *(float2*)&g_fv[((size_t)l*FF + f)*VV + v0] = acc[f];
}

// -------------------- gather + project + sort + level-3 signature ---------------
__global__ void __launch_bounds__(256) k_sig(const int* __restrict__ dgm0,
                                             const int* __restrict__ dgm1rel,
                                             const int* __restrict__ dgm1ext,
                                             const float* __restrict__ Wp,
                                             const float* __restrict__ bp) {
    int bid = blockIdx.x;
    int which = bid & 1;
    int row = bid >> 1;
    int tid = threadIdx.x;
    __shared__ float vals[640];
    __shared__ float srows[7*512];
    __shared__ float s_w0[7], s_w1[7], s_b[7];
    const float* fvr = g_fv + (size_t)row*VV;
    if (tid < 7) { s_w0[tid] = Wp[tid*2]; s_w1[tid] = Wp[tid*2+1]; s_b[tid] = bp[tid]; }
    for (int t = tid; t < 640; t += 256) {
        int src;
        if (which)        src = dgm1ext[row*640 + t];
        else if (t < 512) src = dgm0[row*512 + t];
        else              src = dgm1rel[row*129 + (128 - (t - 512))];
        vals[t] = fvr[src];
    }
    __syncthreads();
    const float PINF = __int_as_float(0x7f800000);
    for (int idx = tid; idx < 7*512; idx += 256) {
        int s = idx >> 9, p = idx & 511;
        float v = PINF;
        if (p < 320) v = fmaf(vals[2*p], s_w0[s], fmaf(vals[2*p+1], s_w1[s], s_b[s]));
        srows[idx] = v;
    }
    __syncthreads();
    int w = tid >> 5, lane = tid & 31;
    if (w < 7) {
        float* a = srows + w*512;
        for (int k = 2; k <= 512; k <<= 1) {
            for (int j = k >> 1; j > 0; j >>= 1) {
                #pragma unroll 1
                for (int i = lane; i < 512; i += 32) {
                    int ixj = i ^ j;
                    if (ixj > i) {
                        float xv = a[i], yv = a[ixj];
                        if ((xv > yv) == ((i & k) == 0)) { a[i] = yv; a[ixj] = xv; }
                    }
                }
                __syncwarp();
            }
        }
    }
    __syncthreads();
    if (tid < 64) {
        int i = tid >> 3, j = tid & 7;
        float s1i = 0.f, s2ij = 0.f;
        float s3[8];
        #pragma unroll
        for (int kk = 0; kk < 8; kk++) s3[kk] = 0.f;
        float cur[7];
        #pragma unroll
        for (int d = 0; d < 7; d++) cur[d] = srows[d*512];
        float dx[8];
        dx[0] = DTT;
        for (int p = 0; p < 319; p++) {
            #pragma unroll
            for (int d = 0; d < 7; d++) {
                float nx = srows[d*512 + p + 1];
                dx[d+1] = nx - cur[d];
                cur[d] = nx;
            }
            float dxi = dx[i], dxj = dx[j];
            float c = fmaf(dxj, fmaf(dxi, (1.f/6.f), 0.5f*s1i), s2ij);
            #pragma unroll
            for (int kk = 0; kk < 8; kk++) s3[kk] = fmaf(c, dx[kk], s3[kk]);
            s2ij = fmaf(dxj, fmaf(0.5f, dxi, s1i), s2ij);
            s1i += dxi;
        }
        int l = row >> 3, fi = row & 7;
        float* out = g_x + l*FINALW + fi*(2*SIGLEN) + which*SIGLEN;
        if (j == 0) out[i] = s1i;
        out[8 + tid] = s2ij;
        #pragma unroll
        for (int kk = 0; kk < 8; kk++) out[72 + tid*8 + kk] = s3[kk];
    }
}

// ----------------------- final dot + BatchNorm over L=32 ------------------------
__global__ void k_final(const float* __restrict__ Wf, const float* __restrict__ gfin,
                        const float* __restrict__ betafin, float* __restrict__ out) {
    int w = threadIdx.x >> 5, lane = threadIdx.x & 31;
    const float* xr = g_x + w*FINALW;
    float p = 0.f;
    for (int i = lane; i < FINALW; i += 32) p = fmaf(xr[i], Wf[i], p);
    #pragma unroll
    for (int o = 16; o > 0; o >>= 1) p += __shfl_down_sync(0xffffffffu, p, o);
    __shared__ double s_out[32];
    if (lane == 0) s_out[w] = p;
    __syncthreads();
    __shared__ double sm[2];
    if (threadIdx.x == 0) {
        double S = 0.0, Q = 0.0;
        for (int i = 0; i < 32; i++) { S += s_out[i]; Q += s_out[i]*s_out[i]; }
        double mean = S/32.0;
        sm[0] = mean; sm[1] = Q/32.0 - mean*mean;
    }
    __syncthreads();
    if (threadIdx.x < 32) {
        double r = (s_out[threadIdx.x] - sm[0]) / sqrt(sm[1] + (double)EPSB);
        out[threadIdx.x] = (float)(r*(double)gfin[0] + (double)betafin[0]);
    }
}

// --------------------------------- launcher -------------------------------------
extern "C" void kernel_launch(void* const* d_in, const int* in_sizes, int n_in,
                              void* d_out, int out_size) {
    const float* eigenvalues = (const float*)d_in[0];
    const float* eigvec      = (const float*)d_in[1];
    const int*   dgm0        = (const int*)d_in[2];
    const int*   dgm1rel     = (const int*)d_in[3];
    const int*   dgm1ext     = (const int*)d_in[4];
    const float* mlp_Win     = (const float*)d_in[5];
    const float* mlp_gin     = (const float*)d_in[7];
    const float* mlp_betain  = (const float*)d_in[8];
    const float* mlp_Wh      = (const float*)d_in[9];
    const float* mlp_gh      = (const float*)d_in[11];
    const float* mlp_betah   = (const float*)d_in[12];
    const float* mlp_Wout    = (const float*)d_in[13];
    const float* mlp_gout    = (const float*)d_in[15];
    const float* mlp_betaout = (const float*)d_in[16];
    const float* W_proj      = (const float*)d_in[17];
    const float* b_proj      = (const float*)d_in[18];
    const float* W_fin       = (const float*)d_in[19];
    const float* g_fin       = (const float*)d_in[21];
    const float* beta_fin    = (const float*)d_in[22];
    float* out = (float*)d_out;

    k_xstats<<<1, 1024>>>(eigenvalues, mlp_Win, mlp_gin, mlp_betain);
    k_gemm<0><<<dim3(256, 8), 256>>>(eigenvalues, mlp_Wh);
    k_bncoef<0><<<8, 1024>>>(mlp_gh, mlp_betah);
    k_gemm<1><<<dim3(256, 8), 256>>>(eigenvalues, mlp_Wh);
    k_bncoef<1><<<8, 1024>>>(mlp_gh, mlp_betah);
    k_out<<<dim3(64, 8), 256>>>(mlp_Wout);
    k_bnO<<<1, 32>>>(mlp_gout, mlp_betaout);
    k_einsum<<<dim3(4, 32), 256>>>(eigvec);
    k_sig<<<512, 256>>>(dgm0, dgm1rel, dgm1ext, W_proj, b_proj);
    k_final<<<1, 1024>>>(W_fin, g_fin, beta_fin, out);
}